// round 9
// baseline (speedup 1.0000x reference)
#include <cuda_runtime.h>
#include <math.h>

#define B_ 32
#define S_ 100
#define T_ 64
#define H_ 512
#define E_ 512
#define V_ 32000
#define BE (B_*E_)

// ----------------------------- device scratch ------------------------------
__device__ __align__(256) float g_xe  [T_*B_*E_];   // gathered embeddings [t][b][e]
__device__ __align__(256) float g_outs[T_*B_*E_];   // out_t for all t  (A of logits GEMM)
__device__ __align__(256) float g_h[2][B_*H_];
__device__ __align__(256) float g_c[2][B_*H_];
__device__ __align__(256) float g_q  [B_*H_];
__device__ __align__(256) float g_ctx[B_*H_];
__device__ __align__(256) float g_t1 [B_*H_];
__device__ __align__(256) float g_Wqb[H_*H_];       // Wb @ Wq   (row-major [i][k])
__device__ __align__(256) float g_bqb[H_];          // Wb @ bq + bb
__device__ int g_trg64;                             // 1 if trg is int64
__device__ int g_mask4;                             // 1 if mask elements are 4-byte

// ------------------------- dtype detection (deterministic) -----------------
__global__ void k_detect(const void* trg, const void* mask){
    if (threadIdx.x == 0){
        // trg: int64 tokens < 32000 have zero high words at odd int32 slots.
        const int* t32 = (const int*)trg;
        int is64 = 1;
        for (int i = 0; i < 256; i++) if (t32[2*i+1] != 0) { is64 = 0; break; }
        g_trg64 = is64;
        // mask: int32/float32 encodings of "true" have bytes 1..3 of word 0
        // distinguishable from an all-true bool byte stream.
        const unsigned char* mb = (const unsigned char*)mask;
        int m4 = 1;
        for (int i = 0; i < 64; i++)
            if (mb[4*i+1] | mb[4*i+2] | mb[4*i+3]) { m4 = 0; break; }
        g_mask4 = m4;
    }
}

// ----------------------------- prologue kernels ----------------------------
__global__ void k_gather(const void* __restrict__ trg, const float* __restrict__ emb){
    int idx = blockIdx.x*256 + threadIdx.x;   // < T*B*E
    int e   = idx & 511;
    int rem = idx >> 9;                       // t*32 + b
    int b   = rem & 31;
    int t   = rem >> 5;
    long long tok = g_trg64 ? ((const long long*)trg)[b*T_ + t]
                            : (long long)((const int*)trg)[b*T_ + t];
    g_xe[idx] = emb[(size_t)tok*E_ + e];
}

__global__ void k_init(const float* __restrict__ h0, const float* __restrict__ c0){
    int i = blockIdx.x*256 + threadIdx.x;     // < B*H
    g_h[0][i] = h0[i];
    g_c[0][i] = c0[i];
}

// Wqb[i][k] = sum_m Wb[i][m] * Wq[m][k]
__global__ void k_wqb(const float* __restrict__ Wb, const float* __restrict__ Wq){
    __shared__ float A[16][17], Bm[16][17];
    int tx = threadIdx.x, ty = threadIdx.y;
    int i = blockIdx.y*16 + ty, k = blockIdx.x*16 + tx;
    float acc = 0.f;
    for (int m0 = 0; m0 < H_; m0 += 16){
        A [ty][tx] = Wb[i*H_ + m0 + tx];
        Bm[ty][tx] = Wq[(m0+ty)*H_ + k];
        __syncthreads();
#pragma unroll
        for (int m = 0; m < 16; m++) acc += A[ty][m]*Bm[m][tx];
        __syncthreads();
    }
    g_Wqb[i*H_ + k] = acc;
}

__global__ void k_bqb(const float* __restrict__ Wb, const float* __restrict__ bq,
                      const float* __restrict__ bb){
    int row  = blockIdx.x*4 + (threadIdx.x >> 5);   // 128 blocks x 4 rows
    int lane = threadIdx.x & 31;
    float s = 0.f;
    for (int m = lane; m < H_; m += 32) s += Wb[row*H_ + m]*bq[m];
#pragma unroll
    for (int o = 16; o; o >>= 1) s += __shfl_xor_sync(0xffffffffu, s, o);
    if (lane == 0) g_bqb[row] = s + bb[row];
}

// ------------- gates GEMM (2048 x 32, K=1536) fused with LSTM cell ---------
// grid 128 blocks x 128 threads; block covers 4 hidden units x 4 gates = 16 rows.
__global__ __launch_bounds__(128) void k_gates(int t,
        const float* __restrict__ W_ih, const float* __restrict__ W_hh,
        const float* __restrict__ b_ih, const float* __restrict__ b_hh,
        const float* __restrict__ init_out){
    __shared__ float Xs[32][68];
    __shared__ float sg[4][4][33];
    int tid = threadIdx.x;
    int rid = tid >> 3, bg = tid & 7;       // 16 rows x 8 batch-groups
    int gidx = rid >> 2, uu = rid & 3;      // gate index, unit-in-block
    int u0  = blockIdx.x*4;
    int row = gidx*512 + u0 + uu;
    const float* xe_t    = g_xe + t*BE;
    const float* outprev = t ? (g_outs + (t-1)*BE) : init_out;
    const float* hprev   = g_h[t & 1];
    float a0 = 0.f, a1 = 0.f, a2 = 0.f, a3 = 0.f;

    for (int kc = 0; kc < 24; kc++){        // 1536 / 64
        int kbase = kc*64;
#pragma unroll
        for (int i = 0; i < 4; i++){
            int f = tid + i*128;
            int b_l = f >> 4, kk4 = (f & 15)*4;
            int kg = kbase + kk4;
            const float* src = (kg < 512)  ? xe_t    + b_l*512 + kg
                             : (kg < 1024) ? outprev + b_l*512 + (kg-512)
                                           : hprev   + b_l*512 + (kg-1024);
            float4 v = *(const float4*)src;
            Xs[b_l][kk4]   = v.x; Xs[b_l][kk4+1] = v.y;
            Xs[b_l][kk4+2] = v.z; Xs[b_l][kk4+3] = v.w;
        }
        __syncthreads();
        const float* wrow = (kbase < 1024) ? (W_ih + row*1024 + kbase)
                                           : (W_hh + row*512 + (kbase-1024));
#pragma unroll
        for (int kk = 0; kk < 64; kk += 4){
            float4 w  = *(const float4*)(wrow + kk);
            float4 x0 = *(const float4*)&Xs[bg   ][kk];
            float4 x1 = *(const float4*)&Xs[bg+ 8][kk];
            float4 x2 = *(const float4*)&Xs[bg+16][kk];
            float4 x3 = *(const float4*)&Xs[bg+24][kk];
            a0 += w.x*x0.x + w.y*x0.y + w.z*x0.z + w.w*x0.w;
            a1 += w.x*x1.x + w.y*x1.y + w.z*x1.z + w.w*x1.w;
            a2 += w.x*x2.x + w.y*x2.y + w.z*x2.z + w.w*x2.w;
            a3 += w.x*x3.x + w.y*x3.y + w.z*x3.z + w.w*x3.w;
        }
        __syncthreads();
    }
    sg[gidx][uu][bg]    = a0;
    sg[gidx][uu][bg+8]  = a1;
    sg[gidx][uu][bg+16] = a2;
    sg[gidx][uu][bg+24] = a3;
    __syncthreads();

    // LSTM cell epilogue: 128 threads = 4 units x 32 batches
    int uu_e = tid >> 5, b_e = tid & 31;
    int ug = u0 + uu_e;
    float iv = sg[0][uu_e][b_e] + b_ih[ug]        + b_hh[ug];
    float fv = sg[1][uu_e][b_e] + b_ih[512+ug]    + b_hh[512+ug];
    float gv = sg[2][uu_e][b_e] + b_ih[1024+ug]   + b_hh[1024+ug];
    float ov = sg[3][uu_e][b_e] + b_ih[1536+ug]   + b_hh[1536+ug];
    float is = 1.f/(1.f + expf(-iv));
    float fs = 1.f/(1.f + expf(-fv));
    float os = 1.f/(1.f + expf(-ov));
    float gt = tanhf(gv);
    float cp = g_c[t & 1][b_e*H_ + ug];
    float cn = fs*cp + is*gt;
    float hn = os*tanhf(cn);
    g_c[(t+1) & 1][b_e*H_ + ug] = cn;
    g_h[(t+1) & 1][b_e*H_ + ug] = hn;
}

// ------------- generic skinny GEMM: 16 rows x 32 batches per block ---------
// mode 0: q' = h @ Wqb^T + bqb               (K=512)
// mode 1: t1 = tanh([h;ctx] @ Wo1^T + bo1)   (K=1024)
// mode 2: out = t1 @ Wo2^T + bo2 -> g_outs[t](K=512)
__global__ __launch_bounds__(128) void k_skinny(int t, int mode, int K,
        const float* __restrict__ Wext, const float* __restrict__ bext){
    __shared__ float Xs[32][68];
    int tid = threadIdx.x;
    int rid = tid >> 3, bg = tid & 7;
    int row = blockIdx.x*16 + rid;
    const float* X0; const float* X1 = 0;
    const float* W;  const float* bias; float* dst;
    if (mode == 0){ X0 = g_h[(t+1)&1];              W = g_Wqb; bias = g_bqb; dst = g_q; }
    else if (mode == 1){ X0 = g_h[(t+1)&1]; X1 = g_ctx; W = Wext; bias = bext; dst = g_t1; }
    else { X0 = g_t1; W = Wext; bias = bext; dst = g_outs + t*BE; }

    float a0 = 0.f, a1 = 0.f, a2 = 0.f, a3 = 0.f;
    int nch = K >> 6;
    for (int kc = 0; kc < nch; kc++){
        int kbase = kc*64;
#pragma unroll
        for (int i = 0; i < 4; i++){
            int f = tid + i*128;
            int b_l = f >> 4, kk4 = (f & 15)*4;
            int kg = kbase + kk4;
            const float* src = (kg < 512) ? X0 + b_l*512 + kg
                                          : X1 + b_l*512 + (kg-512);
            float4 v = *(const float4*)src;
            Xs[b_l][kk4]   = v.x; Xs[b_l][kk4+1] = v.y;
            Xs[b_l][kk4+2] = v.z; Xs[b_l][kk4+3] = v.w;
        }
        __syncthreads();
        const float* wrow = W + row*K + kbase;
#pragma unroll
        for (int kk = 0; kk < 64; kk += 4){
            float4 w  = *(const float4*)(wrow + kk);
            float4 x0 = *(const float4*)&Xs[bg   ][kk];
            float4 x1 = *(const float4*)&Xs[bg+ 8][kk];
            float4 x2 = *(const float4*)&Xs[bg+16][kk];
            float4 x3 = *(const float4*)&Xs[bg+24][kk];
            a0 += w.x*x0.x + w.y*x0.y + w.z*x0.z + w.w*x0.w;
            a1 += w.x*x1.x + w.y*x1.y + w.z*x1.z + w.w*x1.w;
            a2 += w.x*x2.x + w.y*x2.y + w.z*x2.z + w.w*x2.w;
            a3 += w.x*x3.x + w.y*x3.y + w.z*x3.z + w.w*x3.w;
        }
        __syncthreads();
    }
    float bs = bias[row];
    float v0 = a0 + bs, v1 = a1 + bs, v2 = a2 + bs, v3 = a3 + bs;
    if (mode == 1){ v0 = tanhf(v0); v1 = tanhf(v1); v2 = tanhf(v2); v3 = tanhf(v3); }
    dst[(bg   )*512 + row] = v0;
    dst[(bg+ 8)*512 + row] = v1;
    dst[(bg+16)*512 + row] = v2;
    dst[(bg+24)*512 + row] = v3;
}

// ---------------- fused bilinear attention (scores+softmax+ctx) ------------
__global__ __launch_bounds__(256) void k_attn(const float* __restrict__ mem,
                                              const void* __restrict__ mask){
    __shared__ float qv[H_];
    __shared__ float sw[128];
    int b = blockIdx.x, tid = threadIdx.x;
    qv[tid]     = g_q[b*H_ + tid];
    qv[tid+256] = g_q[b*H_ + tid + 256];
    __syncthreads();

    int w = tid >> 5, lane = tid & 31;
    const float* memb = mem + (size_t)b*S_*H_;
    for (int s = w; s < S_; s += 8){
        const float* m = memb + s*H_;
        float sum = 0.f;
#pragma unroll
        for (int h = lane; h < H_; h += 32) sum += qv[h]*m[h];
#pragma unroll
        for (int o = 16; o; o >>= 1) sum += __shfl_xor_sync(0xffffffffu, sum, o);
        if (lane == 0){
            bool mv = g_mask4 ? (((const int*)mask)[b*S_ + s] != 0)
                              : (((const unsigned char*)mask)[b*S_ + s] != 0);
            sw[s] = mv ? sum : -1e9f;
        }
    }
    __syncthreads();
    if (tid < 32){
        float mx = -1e30f;
        for (int s = lane; s < S_; s += 32) mx = fmaxf(mx, sw[s]);
#pragma unroll
        for (int o = 16; o; o >>= 1) mx = fmaxf(mx, __shfl_xor_sync(0xffffffffu, mx, o));
        float ev[4]; float ps = 0.f;
#pragma unroll
        for (int j = 0; j < 4; j++){
            int s = lane + j*32;
            float e = (s < S_) ? expf(sw[s] - mx) : 0.f;
            ev[j] = e; ps += e;
        }
#pragma unroll
        for (int o = 16; o; o >>= 1) ps += __shfl_xor_sync(0xffffffffu, ps, o);
        float inv = 1.f/ps;
#pragma unroll
        for (int j = 0; j < 4; j++){
            int s = lane + j*32;
            if (s < S_) sw[s] = ev[j]*inv;
        }
    }
    __syncthreads();
    for (int h = tid; h < H_; h += 256){
        float c = 0.f;
        for (int s = 0; s < S_; s++) c += sw[s]*memb[s*H_ + h];
        g_ctx[b*H_ + h] = c;
    }
}

// ---------------- tf32 logits GEMM: (2048 x 32000) @ K=512 -----------------
__device__ __forceinline__ unsigned f2t(float f){
    unsigned u;
    asm("cvt.rna.tf32.f32 %0, %1;" : "=r"(u) : "f"(f));
    return u;
}

__global__ __launch_bounds__(256) void k_logits(const float* __restrict__ emb,
                                                float* __restrict__ out){
    __shared__ unsigned As[128][36];
    __shared__ unsigned Bs[128][36];
    int tid = threadIdx.x;
    int m0 = blockIdx.y*128;
    int n0 = blockIdx.x*128;
    int warp = tid >> 5, lane = tid & 31;
    int wm = (warp & 1)*64, wn = (warp >> 1)*32;   // 2x4 warp grid, warp tile 64x32
    int g = lane >> 2, tg = lane & 3;
    float c[4][4][4];
#pragma unroll
    for (int mt = 0; mt < 4; mt++)
#pragma unroll
    for (int nt = 0; nt < 4; nt++)
#pragma unroll
    for (int r = 0; r < 4; r++) c[mt][nt][r] = 0.f;

    for (int kc = 0; kc < 16; kc++){
        int k0 = kc*32;
#pragma unroll
        for (int i = 0; i < 4; i++){
            int f = tid + i*256;
            int r = f >> 3, k4 = (f & 7)*4;
            float4 va = *(const float4*)(g_outs + (size_t)(m0+r)*512 + k0 + k4);
            As[r][k4]   = f2t(va.x); As[r][k4+1] = f2t(va.y);
            As[r][k4+2] = f2t(va.z); As[r][k4+3] = f2t(va.w);
            float4 vb = *(const float4*)(emb + (size_t)(n0+r)*512 + k0 + k4);
            Bs[r][k4]   = f2t(vb.x); Bs[r][k4+1] = f2t(vb.y);
            Bs[r][k4+2] = f2t(vb.z); Bs[r][k4+3] = f2t(vb.w);
        }
        __syncthreads();
#pragma unroll
        for (int ks = 0; ks < 4; ks++){
            unsigned a[4][4], bf[4][2];
#pragma unroll
            for (int mt = 0; mt < 4; mt++){
                int rr = wm + mt*16 + g;
                a[mt][0] = As[rr  ][ks*8+tg];
                a[mt][1] = As[rr+8][ks*8+tg];
                a[mt][2] = As[rr  ][ks*8+tg+4];
                a[mt][3] = As[rr+8][ks*8+tg+4];
            }
#pragma unroll
            for (int nt = 0; nt < 4; nt++){
                int rr = wn + nt*8 + g;
                bf[nt][0] = Bs[rr][ks*8+tg];
                bf[nt][1] = Bs[rr][ks*8+tg+4];
            }
#pragma unroll
            for (int mt = 0; mt < 4; mt++)
#pragma unroll
            for (int nt = 0; nt < 4; nt++){
                asm volatile(
                    "mma.sync.aligned.m16n8k8.row.col.f32.tf32.tf32.f32 "
                    "{%0,%1,%2,%3}, {%4,%5,%6,%7}, {%8,%9}, {%0,%1,%2,%3};\n"
                    : "+f"(c[mt][nt][0]), "+f"(c[mt][nt][1]),
                      "+f"(c[mt][nt][2]), "+f"(c[mt][nt][3])
                    : "r"(a[mt][0]), "r"(a[mt][1]), "r"(a[mt][2]), "r"(a[mt][3]),
                      "r"(bf[nt][0]), "r"(bf[nt][1]));
            }
        }
        __syncthreads();
    }
    // epilogue: m = t*32 + b  ->  out[b][t][n]
#pragma unroll
    for (int mt = 0; mt < 4; mt++){
        int m1 = m0 + wm + mt*16 + g;
        int m2 = m1 + 8;
        int t1 = m1 >> 5, b1 = m1 & 31;
        int t2 = m2 >> 5, b2 = m2 & 31;
#pragma unroll
        for (int nt = 0; nt < 4; nt++){
            int n = n0 + wn + nt*8 + tg*2;
            float2* p1 = (float2*)(out + (size_t)b1*T_*V_ + (size_t)t1*V_ + n);
            *p1 = make_float2(c[mt][nt][0], c[mt][nt][1]);
            float2* p2 = (float2*)(out + (size_t)b2*T_*V_ + (size_t)t2*V_ + n);
            *p2 = make_float2(c[mt][nt][2], c[mt][nt][3]);
        }
    }
}

// ------------------------------- launch ------------------------------------
extern "C" void kernel_launch(void* const* d_in, const int* in_sizes, int n_in,
                              void* d_out, int out_size){
    const float* src_memory  = (const float*)d_in[0];
    const void*  src_mask    = d_in[1];
    const float* init_hidden = (const float*)d_in[2];
    const float* init_cell   = (const float*)d_in[3];
    const float* init_output = (const float*)d_in[4];
    const void*  trg         = d_in[5];
    const float* emb         = (const float*)d_in[6];
    const float* W_ih        = (const float*)d_in[7];
    const float* W_hh        = (const float*)d_in[8];
    const float* b_ih        = (const float*)d_in[9];
    const float* b_hh        = (const float*)d_in[10];
    const float* Wq          = (const float*)d_in[11];
    const float* bq          = (const float*)d_in[12];
    const float* Wb          = (const float*)d_in[13];
    const float* bb          = (const float*)d_in[14];
    const float* Wo1         = (const float*)d_in[15];
    const float* bo1         = (const float*)d_in[16];
    const float* Wo2         = (const float*)d_in[17];
    const float* bo2         = (const float*)d_in[18];
    float* out = (float*)d_out;

    k_detect<<<1, 32>>>(trg, src_mask);
    k_gather<<<(T_*B_*E_)/256, 256>>>(trg, emb);
    k_init<<<(B_*H_)/256, 256>>>(init_hidden, init_cell);
    k_wqb<<<dim3(32,32), dim3(16,16)>>>(Wb, Wq);
    k_bqb<<<128, 128>>>(Wb, bq, bb);

    for (int t = 0; t < T_; t++){
        k_gates<<<128, 128>>>(t, W_ih, W_hh, b_ih, b_hh, init_output);
        k_skinny<<<32, 128>>>(t, 0, 512, (const float*)0, (const float*)0);
        k_attn<<<32, 256>>>(src_memory, src_mask);
        k_skinny<<<32, 128>>>(t, 1, 1024, Wo1, bo1);
        k_skinny<<<32, 128>>>(t, 2, 512, Wo2, bo2);
    }

    k_logits<<<dim3(V_/128, (T_*B_)/128), 256>>>(emb, out);
}

// round 12
// speedup vs baseline: 2.4364x; 2.4364x over previous
#include <cuda_runtime.h>
#include <math.h>

#define B_ 32
#define S_ 100
#define T_ 64
#define H_ 512
#define E_ 512
#define V_ 32000
#define BE (B_*E_)
#define BH (B_*H_)
#define NBLK 128
#define NTHR 256

// ----------------------------- device scratch ------------------------------
__device__ __align__(256) float g_xe  [T_*B_*E_];   // gathered embeddings [t][b][e]
__device__ __align__(256) float g_outs[T_*B_*E_];   // out_t for all t  (A of logits GEMM)
__device__ __align__(256) float g_h[2][BH];
__device__ __align__(256) float g_q   [BH];
__device__ __align__(256) float g_ctxp[4*BH];       // partial ctx per s-quad
__device__ __align__(256) float g_t1  [BH];
__device__ __align__(256) float g_sc  [B_*100];     // raw scores
__device__ __align__(256) float g_Wqb [H_*H_];      // Wb @ Wq
__device__ __align__(256) float g_bqb [H_];         // Wb @ bq + bb
__device__ unsigned long long g_barc;               // grid-barrier counter (monotone)
__device__ int g_trg64;
__device__ int g_mask4;

// ---------------------- smem layout (floats) --------------------------------
#define OFF_SW   0                        // 16 x 1544 gate rows
#define OFF_SM   24704                    // 25 x 516  src_memory slice
#define OFF_SQB  37604                    // 4 x 512
#define OFF_SO1  39652                    // 4 x 1024
#define OFF_SO2  43748                    // 4 x 512
#define OFF_XS   45796                    // 2 x 32 x 68
#define OFF_SCR  50148                    // 1024
#define OFF_SC   51172                    // 128 cell state
#define SMEM_FLOATS 51300
#define SMEM_BYTES (SMEM_FLOATS*4)

// ------------------------- dtype detection ----------------------------------
__global__ void k_detect(const void* trg, const void* mask){
    if (threadIdx.x == 0){
        const int* t32 = (const int*)trg;
        int is64 = 1;
        for (int i = 0; i < 256; i++) if (t32[2*i+1] != 0) { is64 = 0; break; }
        g_trg64 = is64;
        const unsigned char* mb = (const unsigned char*)mask;
        int m4 = 1;
        for (int i = 0; i < 64; i++)
            if (mb[4*i+1] | mb[4*i+2] | mb[4*i+3]) { m4 = 0; break; }
        g_mask4 = m4;
    }
}

// ----------------------------- prologue kernels ------------------------------
__global__ void k_gather(const void* __restrict__ trg, const float* __restrict__ emb){
    int idx = blockIdx.x*256 + threadIdx.x;
    int e   = idx & 511;
    int rem = idx >> 9;
    int b   = rem & 31;
    int t   = rem >> 5;
    long long tok = g_trg64 ? ((const long long*)trg)[b*T_ + t]
                            : (long long)((const int*)trg)[b*T_ + t];
    g_xe[idx] = emb[(size_t)tok*E_ + e];
}

__global__ void k_init(const float* __restrict__ h0){
    int i = blockIdx.x*256 + threadIdx.x;
    g_h[0][i] = h0[i];
}

__global__ void k_wqb(const float* __restrict__ Wb, const float* __restrict__ Wq){
    __shared__ float A[16][17], Bm[16][17];
    int tx = threadIdx.x, ty = threadIdx.y;
    int i = blockIdx.y*16 + ty, k = blockIdx.x*16 + tx;
    float acc = 0.f;
    for (int m0 = 0; m0 < H_; m0 += 16){
        A [ty][tx] = Wb[i*H_ + m0 + tx];
        Bm[ty][tx] = Wq[(m0+ty)*H_ + k];
        __syncthreads();
#pragma unroll
        for (int m = 0; m < 16; m++) acc += A[ty][m]*Bm[m][tx];
        __syncthreads();
    }
    g_Wqb[i*H_ + k] = acc;
}

__global__ void k_bqb(const float* __restrict__ Wb, const float* __restrict__ bq,
                      const float* __restrict__ bb){
    int row  = blockIdx.x*4 + (threadIdx.x >> 5);
    int lane = threadIdx.x & 31;
    float s = 0.f;
    for (int m = lane; m < H_; m += 32) s += Wb[row*H_ + m]*bq[m];
#pragma unroll
    for (int o = 16; o; o >>= 1) s += __shfl_xor_sync(0xffffffffu, s, o);
    if (lane == 0) g_bqb[row] = s + bb[row];
}

// --------------------------- grid barrier -----------------------------------
__device__ __forceinline__ void gbar(){
    __syncthreads();
    if (threadIdx.x == 0){
        __threadfence();
        unsigned long long my = atomicAdd(&g_barc, 1ULL);
        unsigned long long target = ((my >> 7) + 1ULL) << 7;   // (epoch+1)*128
        while (atomicAdd(&g_barc, 0ULL) < target) { __nanosleep(200); }
        __threadfence();
    }
    __syncthreads();
}

// ------------- generic skinny phase: 4 rows x 32 batches, smem W ------------
// ctx4 != 0: for kg >= 512 the X source is the SUM of 4 g_ctxp partials.
__device__ __forceinline__ void phase_skinny(
    float* XS, float* SCR, const float* Wsm, int K,
    const float* X0, const float* X1, int ctx4,
    const float* bias, int row0, float* dst, bool do_tanh)
{
    int tid = threadIdx.x;
    int nch = K >> 6;
    float4 pre[2];
#define SK_LOAD(c) { \
    _Pragma("unroll") \
    for (int i = 0; i < 2; i++){ \
        int f = tid*2 + i; int bl = f >> 4; int kk4 = (f & 15)*4; \
        int kg = (c)*64 + kk4; \
        if (kg < 512){ \
            pre[i] = __ldcg((const float4*)(X0 + bl*512 + kg)); \
        } else if (!ctx4){ \
            pre[i] = __ldcg((const float4*)(X1 + bl*512 + (kg-512))); \
        } else { \
            const float4* p = (const float4*)(X1 + bl*512 + (kg-512)); \
            float4 v0 = __ldcg(p); \
            float4 v1 = __ldcg(p + BH/4); \
            float4 v2 = __ldcg(p + 2*(BH/4)); \
            float4 v3 = __ldcg(p + 3*(BH/4)); \
            pre[i] = make_float4(v0.x+v1.x+v2.x+v3.x, v0.y+v1.y+v2.y+v3.y, \
                                 v0.z+v1.z+v2.z+v3.z, v0.w+v1.w+v2.w+v3.w); \
        } } }
#define SK_STS(c) { \
    _Pragma("unroll") \
    for (int i = 0; i < 2; i++){ \
        int f = tid*2 + i; int bl = f >> 4; int kk4 = (f & 15)*4; \
        *(float4*)(XS + (((c)&1)*32 + bl)*68 + kk4) = pre[i]; } }
    SK_LOAD(0); SK_STS(0); __syncthreads();
    int rr = tid >> 6, half = (tid >> 5) & 1, b = tid & 31;
    const float* wb = Wsm + rr*K + half*32;
    float acc = 0.f;
    for (int c = 0; c < nch; c++){
        if (c+1 < nch) SK_LOAD(c+1);
        const float* xb = XS + ((c&1)*32 + b)*68 + half*32;
        const float* wr = wb + c*64;
#pragma unroll
        for (int kk = 0; kk < 32; kk += 4){
            float4 w = *(const float4*)(wr + kk);
            float4 x = *(const float4*)(xb + kk);
            acc += w.x*x.x + w.y*x.y + w.z*x.z + w.w*x.w;
        }
        if (c+1 < nch){ SK_STS(c+1); __syncthreads(); }
    }
    __syncthreads();
    SCR[rr*64 + half*32 + b] = acc;
    __syncthreads();
    if (tid < 128){
        int r2 = tid >> 5, b2 = tid & 31;
        float v = SCR[r2*64 + b2] + SCR[r2*64 + 32 + b2] + bias[row0 + r2];
        if (do_tanh) v = tanhf(v);
        dst[b2*512 + row0 + r2] = v;
    }
#undef SK_LOAD
#undef SK_STS
}

// -------------------- the persistent 64-step chain kernel -------------------
__global__ __launch_bounds__(NTHR, 1) void k_persist(
    const float* __restrict__ W_ih, const float* __restrict__ W_hh,
    const float* __restrict__ b_ih, const float* __restrict__ b_hh,
    const float* __restrict__ Wo1,  const float* __restrict__ bo1,
    const float* __restrict__ Wo2,  const float* __restrict__ bo2,
    const float* __restrict__ src_memory, const void* __restrict__ mask,
    const float* __restrict__ init_cell,  const float* __restrict__ init_output)
{
    extern __shared__ float smem[];
    float* SW  = smem + OFF_SW;
    float* SM  = smem + OFF_SM;
    float* SQB = smem + OFF_SQB;
    float* SO1 = smem + OFF_SO1;
    float* SO2 = smem + OFF_SO2;
    float* XS  = smem + OFF_XS;
    float* SCR = smem + OFF_SCR;
    float* SC  = smem + OFF_SC;

    int tid = threadIdx.x;
    int blk = blockIdx.x;
    int u0  = blk*4;               // unit / row base for row-partitioned phases
    int ab  = blk & 31;            // attn batch
    int sq  = blk >> 5;            // attn s-quad

    // ---------------- one-time smem population ----------------
    for (int idx = tid; idx < 6144; idx += NTHR){      // 16 gate rows x 384 float4
        int r = idx / 384, j = idx % 384;
        int grow = (r >> 2)*512 + u0 + (r & 3);
        int kg = j*4;
        float4 v = (kg < 1024) ? *(const float4*)(W_ih + (size_t)grow*1024 + kg)
                               : *(const float4*)(W_hh + (size_t)grow*512 + (kg-1024));
        *(float4*)(SW + r*1544 + kg) = v;
    }
    for (int idx = tid; idx < 3200; idx += NTHR){      // 25 s x 128 float4
        int i = idx >> 7, j = idx & 127;
        float4 v = *(const float4*)(src_memory + ((size_t)ab*S_ + sq*25 + i)*H_ + j*4);
        *(float4*)(SM + i*516 + j*4) = v;
    }
    for (int idx = tid; idx < 512; idx += NTHR){       // Wqb 4 rows
        int rr = idx >> 7, j = idx & 127;
        *(float4*)(SQB + rr*512 + j*4) = *(const float4*)(g_Wqb + (size_t)(u0+rr)*512 + j*4);
    }
    for (int idx = tid; idx < 1024; idx += NTHR){      // Wo1 4 rows x 256 float4
        int rr = idx >> 8, j = idx & 255;
        *(float4*)(SO1 + rr*1024 + j*4) = *(const float4*)(Wo1 + (size_t)(u0+rr)*1024 + j*4);
    }
    for (int idx = tid; idx < 512; idx += NTHR){       // Wo2 4 rows x 128 float4
        int rr = idx >> 7, j = idx & 127;
        *(float4*)(SO2 + rr*512 + j*4) = *(const float4*)(Wo2 + (size_t)(u0+rr)*512 + j*4);
    }
    if (tid < 128){                                    // cell init [uu*32 + b]
        int uu = tid >> 5, b = tid & 31;
        SC[tid] = init_cell[b*H_ + u0 + uu];
    }
    __syncthreads();

    for (int t = 0; t < T_; t++){
        // ---------------- phase 1: gates GEMM + LSTM cell ----------------
        {
            const float* xe_t    = g_xe + (size_t)t*BE;
            const float* outprev = t ? g_outs + (size_t)(t-1)*BE : init_output;
            const float* hprev   = g_h[t & 1];
            float4 pre[2];
#define G_LOAD(c) { \
    _Pragma("unroll") \
    for (int i = 0; i < 2; i++){ \
        int f = tid*2 + i; int bl = f >> 4; int kk4 = (f & 15)*4; \
        int kg = (c)*64 + kk4; \
        const float* s = (kg < 512)  ? xe_t    + bl*512 + kg \
                       : (kg < 1024) ? outprev + bl*512 + (kg-512) \
                                     : hprev   + bl*512 + (kg-1024); \
        pre[i] = __ldcg((const float4*)s); } }
#define G_STS(c) { \
    _Pragma("unroll") \
    for (int i = 0; i < 2; i++){ \
        int f = tid*2 + i; int bl = f >> 4; int kk4 = (f & 15)*4; \
        *(float4*)(XS + (((c)&1)*32 + bl)*68 + kk4) = pre[i]; } }
            G_LOAD(0); G_STS(0); __syncthreads();
            int rid = tid >> 4, bg = tid & 15;
            const float* wbase = SW + rid*1544;
            float a0 = 0.f, a1 = 0.f;
            for (int c = 0; c < 24; c++){
                if (c < 23) G_LOAD(c+1);
                const float* xb0 = XS + ((c&1)*32 + bg)*68;
                const float* xb1 = XS + ((c&1)*32 + bg + 16)*68;
                const float* wr  = wbase + c*64;
#pragma unroll
                for (int kk = 0; kk < 64; kk += 4){
                    float4 w  = *(const float4*)(wr  + kk);
                    float4 x0 = *(const float4*)(xb0 + kk);
                    float4 x1 = *(const float4*)(xb1 + kk);
                    a0 += w.x*x0.x + w.y*x0.y + w.z*x0.z + w.w*x0.w;
                    a1 += w.x*x1.x + w.y*x1.y + w.z*x1.z + w.w*x1.w;
                }
                if (c < 23){ G_STS(c+1); __syncthreads(); }
            }
            __syncthreads();
            SCR[rid*33 + bg]      = a0;
            SCR[rid*33 + bg + 16] = a1;
            __syncthreads();
            if (tid < 128){
                int uu = tid >> 5, b = tid & 31;
                int u  = u0 + uu;
                float iv = SCR[(0*4+uu)*33 + b] + b_ih[u]         + b_hh[u];
                float fv = SCR[(1*4+uu)*33 + b] + b_ih[512 + u]   + b_hh[512 + u];
                float gv = SCR[(2*4+uu)*33 + b] + b_ih[1024 + u]  + b_hh[1024 + u];
                float ov = SCR[(3*4+uu)*33 + b] + b_ih[1536 + u]  + b_hh[1536 + u];
                float is = 1.f/(1.f + expf(-iv));
                float fs = 1.f/(1.f + expf(-fv));
                float os = 1.f/(1.f + expf(-ov));
                float gt = tanhf(gv);
                float cn = fs*SC[tid] + is*gt;
                SC[tid] = cn;
                g_h[(t+1) & 1][b*H_ + u] = os*tanhf(cn);
            }
#undef G_LOAD
#undef G_STS
        }
        gbar();

        // ---------------- phase 2: q = h @ Wqb^T + bqb ----------------
        phase_skinny(XS, SCR, SQB, 512, g_h[(t+1)&1], (const float*)0, 0,
                     g_bqb, u0, g_q, false);
        gbar();

        // ---------------- phase 3: scores (25 s per block) ----------------
        {
            if (tid < 128)
                ((float4*)SCR)[tid] = __ldcg((const float4*)(g_q + ab*H_ + tid*4));
            __syncthreads();
            int w = tid >> 5, lane = tid & 31;
            for (int si = w; si < 25; si += 8){
                float sum = 0.f;
#pragma unroll
                for (int j = 0; j < 4; j++){
                    int k = lane*4 + j*128;
                    float4 qv = *(const float4*)(SCR + k);
                    float4 mv = *(const float4*)(SM + si*516 + k);
                    sum += qv.x*mv.x + qv.y*mv.y + qv.z*mv.z + qv.w*mv.w;
                }
#pragma unroll
                for (int o = 16; o; o >>= 1) sum += __shfl_xor_sync(0xffffffffu, sum, o);
                if (lane == 0){
                    int sg = sq*25 + si;
                    bool mv = g_mask4 ? (__ldcg((const int*)mask + ab*S_ + sg) != 0)
                                      : (((const unsigned char*)mask)[ab*S_ + sg] != 0);
                    g_sc[ab*100 + sg] = mv ? sum : -1e9f;
                }
            }
        }
        gbar();

        // -------- phase 4: softmax (redundant) + partial ctx over own quad --------
        {
            if (tid < 25)
                ((float4*)SCR)[tid] = __ldcg((const float4*)(g_sc + ab*100 + tid*4));
            __syncthreads();
            if (tid < 32){
                int lane = tid;
                float mx = -1e30f;
#pragma unroll
                for (int j = 0; j < 4; j++){
                    int s = lane + j*32;
                    if (s < 100) mx = fmaxf(mx, SCR[s]);
                }
#pragma unroll
                for (int o = 16; o; o >>= 1) mx = fmaxf(mx, __shfl_xor_sync(0xffffffffu, mx, o));
                float ps = 0.f;
#pragma unroll
                for (int j = 0; j < 4; j++){
                    int s = lane + j*32;
                    if (s < 100) ps += expf(SCR[s] - mx);
                }
#pragma unroll
                for (int o = 16; o; o >>= 1) ps += __shfl_xor_sync(0xffffffffu, ps, o);
                if (lane == 0){ SCR[120] = mx; SCR[121] = 1.f/ps; }
            }
            __syncthreads();
            if (tid < 25)
                SCR[128 + tid] = expf(SCR[sq*25 + tid] - SCR[120]) * SCR[121];
            __syncthreads();
            float c0 = 0.f, c1 = 0.f;
            int h0 = tid, h1 = tid + 256;
            for (int s = 0; s < 25; s++){
                float ws = SCR[128 + s];
                c0 += ws * SM[s*516 + h0];
                c1 += ws * SM[s*516 + h1];
            }
            g_ctxp[sq*BH + ab*H_ + h0] = c0;
            g_ctxp[sq*BH + ab*H_ + h1] = c1;
        }
        gbar();

        // ---- phase 5: t1 = tanh([h; sum4(ctxp)] @ Wo1^T + bo1) ----
        phase_skinny(XS, SCR, SO1, 1024, g_h[(t+1)&1], g_ctxp, 1,
                     bo1, u0, g_t1, true);
        gbar();

        // ---- phase 6: out = t1 @ Wo2^T + bo2 ----
        phase_skinny(XS, SCR, SO2, 512, g_t1, (const float*)0, 0,
                     bo2, u0, g_outs + (size_t)t*BE, false);
        gbar();
    }
}

// ---------------- tf32 logits GEMM: (2048 x 32000) @ K=512 -----------------
__device__ __forceinline__ unsigned f2t(float f){
    unsigned u;
    asm("cvt.rna.tf32.f32 %0, %1;" : "=r"(u) : "f"(f));
    return u;
}

__global__ __launch_bounds__(256) void k_logits(const float* __restrict__ emb,
                                                float* __restrict__ out){
    __shared__ unsigned As[128][36];
    __shared__ unsigned Bs[128][36];
    int tid = threadIdx.x;
    int m0 = blockIdx.y*128;
    int n0 = blockIdx.x*128;
    int warp = tid >> 5, lane = tid & 31;
    int wm = (warp & 1)*64, wn = (warp >> 1)*32;
    int g = lane >> 2, tg = lane & 3;
    float c[4][4][4];
#pragma unroll
    for (int mt = 0; mt < 4; mt++)
#pragma unroll
    for (int nt = 0; nt < 4; nt++)
#pragma unroll
    for (int r = 0; r < 4; r++) c[mt][nt][r] = 0.f;

    for (int kc = 0; kc < 16; kc++){
        int k0 = kc*32;
#pragma unroll
        for (int i = 0; i < 4; i++){
            int f = tid + i*256;
            int r = f >> 3, k4 = (f & 7)*4;
            float4 va = *(const float4*)(g_outs + (size_t)(m0+r)*512 + k0 + k4);
            As[r][k4]   = f2t(va.x); As[r][k4+1] = f2t(va.y);
            As[r][k4+2] = f2t(va.z); As[r][k4+3] = f2t(va.w);
            float4 vb = *(const float4*)(emb + (size_t)(n0+r)*512 + k0 + k4);
            Bs[r][k4]   = f2t(vb.x); Bs[r][k4+1] = f2t(vb.y);
            Bs[r][k4+2] = f2t(vb.z); Bs[r][k4+3] = f2t(vb.w);
        }
        __syncthreads();
#pragma unroll
        for (int ks = 0; ks < 4; ks++){
            unsigned a[4][4], bf[4][2];
#pragma unroll
            for (int mt = 0; mt < 4; mt++){
                int rr = wm + mt*16 + g;
                a[mt][0] = As[rr  ][ks*8+tg];
                a[mt][1] = As[rr+8][ks*8+tg];
                a[mt][2] = As[rr  ][ks*8+tg+4];
                a[mt][3] = As[rr+8][ks*8+tg+4];
            }
#pragma unroll
            for (int nt = 0; nt < 4; nt++){
                int rr = wn + nt*8 + g;
                bf[nt][0] = Bs[rr][ks*8+tg];
                bf[nt][1] = Bs[rr][ks*8+tg+4];
            }
#pragma unroll
            for (int mt = 0; mt < 4; mt++)
#pragma unroll
            for (int nt = 0; nt < 4; nt++){
                asm volatile(
                    "mma.sync.aligned.m16n8k8.row.col.f32.tf32.tf32.f32 "
                    "{%0,%1,%2,%3}, {%4,%5,%6,%7}, {%8,%9}, {%0,%1,%2,%3};\n"
                    : "+f"(c[mt][nt][0]), "+f"(c[mt][nt][1]),
                      "+f"(c[mt][nt][2]), "+f"(c[mt][nt][3])
                    : "r"(a[mt][0]), "r"(a[mt][1]), "r"(a[mt][2]), "r"(a[mt][3]),
                      "r"(bf[nt][0]), "r"(bf[nt][1]));
            }
        }
        __syncthreads();
    }
#pragma unroll
    for (int mt = 0; mt < 4; mt++){
        int m1 = m0 + wm + mt*16 + g;
        int m2 = m1 + 8;
        int t1 = m1 >> 5, b1 = m1 & 31;
        int t2 = m2 >> 5, b2 = m2 & 31;
#pragma unroll
        for (int nt = 0; nt < 4; nt++){
            int n = n0 + wn + nt*8 + tg*2;
            float2* p1 = (float2*)(out + (size_t)b1*T_*V_ + (size_t)t1*V_ + n);
            *p1 = make_float2(c[mt][nt][0], c[mt][nt][1]);
            float2* p2 = (float2*)(out + (size_t)b2*T_*V_ + (size_t)t2*V_ + n);
            *p2 = make_float2(c[mt][nt][2], c[mt][nt][3]);
        }
    }
}

// ------------------------------- launch ------------------------------------
extern "C" void kernel_launch(void* const* d_in, const int* in_sizes, int n_in,
                              void* d_out, int out_size){
    const float* src_memory  = (const float*)d_in[0];
    const void*  src_mask    = d_in[1];
    const float* init_hidden = (const float*)d_in[2];
    const float* init_cell   = (const float*)d_in[3];
    const float* init_output = (const float*)d_in[4];
    const void*  trg         = d_in[5];
    const float* emb         = (const float*)d_in[6];
    const float* W_ih        = (const float*)d_in[7];
    const float* W_hh        = (const float*)d_in[8];
    const float* b_ih        = (const float*)d_in[9];
    const float* b_hh        = (const float*)d_in[10];
    const float* Wq          = (const float*)d_in[11];
    const float* bq          = (const float*)d_in[12];
    const float* Wb          = (const float*)d_in[13];
    const float* bb          = (const float*)d_in[14];
    const float* Wo1         = (const float*)d_in[15];
    const float* bo1         = (const float*)d_in[16];
    const float* Wo2         = (const float*)d_in[17];
    const float* bo2         = (const float*)d_in[18];
    float* out = (float*)d_out;

    cudaFuncSetAttribute(k_persist,
        cudaFuncAttributeMaxDynamicSharedMemorySize, SMEM_BYTES);

    k_detect<<<1, 32>>>(trg, src_mask);
    k_gather<<<(T_*B_*E_)/256, 256>>>(trg, emb);
    k_init<<<BH/256, 256>>>(init_hidden);
    k_wqb<<<dim3(32,32), dim3(16,16)>>>(Wb, Wq);
    k_bqb<<<128, 128>>>(Wb, bq, bb);

    k_persist<<<NBLK, NTHR, SMEM_BYTES>>>(
        W_ih, W_hh, b_ih, b_hh, Wo1, bo1, Wo2, bo2,
        src_memory, src_mask, init_cell, init_output);

    k_logits<<<dim3(V_/128, (T_*B_)/128), 256>>>(emb, out);
}

// round 14
// speedup vs baseline: 2.9113x; 1.1949x over previous
#include <cuda_runtime.h>
#include <math.h>

#define B_ 32
#define S_ 100
#define T_ 64
#define H_ 512
#define E_ 512
#define V_ 32000
#define BE (B_*E_)
#define BH (B_*H_)
#define NBLK 128
#define NTHR 256

// ----------------------------- device scratch ------------------------------
__device__ __align__(256) float g_xe  [T_*B_*E_];   // gathered embeddings [t][b][e]
__device__ __align__(256) float g_outs[T_*B_*E_];   // out_t for all t  (A of logits GEMM)
__device__ __align__(256) float g_h[2][BH];
__device__ __align__(256) float g_ctxp[4*BH];       // partial ctx per s-quad
__device__ __align__(256) float g_t1  [BH];
__device__ __align__(256) float g_sc  [B_*100];     // raw scores
__device__ __align__(256) float g_Wqb [H_*H_];      // Wb @ Wq
__device__ __align__(256) float g_bqb [H_];         // Wb @ bq + bb
__device__ __align__(256) float g_mem2[B_*100*H_];  // Wqb^T @ m  per (b,s)
__device__ __align__(256) float g_sb  [B_*100];     // bqb . m
__device__ __align__(256) unsigned long long g_flag[NBLK];
__device__ unsigned long long g_rel;
__device__ unsigned long long g_ebase;
__device__ int g_trg64;
__device__ int g_mask4;

// ---------------------- smem layout (floats) --------------------------------
#define OFF_SW   0                        // 16 x 1544 gate rows
#define OFF_SM   24704                    // 25 x 516  src_memory slice
#define OFF_SO1  37604                    // 4 x 1024
#define OFF_SO2  41700                    // 4 x 512
#define OFF_XS   43748                    // 2 x 32 x 68
#define OFF_SCR  48100                    // 1024
#define OFF_SC   49124                    // 128 cell state
#define SMEM_FLOATS 49252
#define SMEM_BYTES (SMEM_FLOATS*4)

// ------------------------- acquire/release helpers ---------------------------
__device__ __forceinline__ unsigned long long ld_acq(const unsigned long long* p){
    unsigned long long v;
    asm volatile("ld.acquire.gpu.u64 %0, [%1];" : "=l"(v) : "l"(p) : "memory");
    return v;
}
__device__ __forceinline__ void st_rel(unsigned long long* p, unsigned long long v){
    asm volatile("st.release.gpu.u64 [%0], %1;" :: "l"(p), "l"(v) : "memory");
}

// ------------------------- dtype detection ----------------------------------
__global__ void k_detect(const void* trg, const void* mask){
    if (threadIdx.x == 0){
        const int* t32 = (const int*)trg;
        int is64 = 1;
        for (int i = 0; i < 256; i++) if (t32[2*i+1] != 0) { is64 = 0; break; }
        g_trg64 = is64;
        const unsigned char* mb = (const unsigned char*)mask;
        int m4 = 1;
        for (int i = 0; i < 64; i++)
            if (mb[4*i+1] | mb[4*i+2] | mb[4*i+3]) { m4 = 0; break; }
        g_mask4 = m4;
    }
}

// ----------------------------- prologue kernels ------------------------------
__global__ void k_gather(const void* __restrict__ trg, const float* __restrict__ emb){
    int idx = blockIdx.x*256 + threadIdx.x;
    int e   = idx & 511;
    int rem = idx >> 9;
    int b   = rem & 31;
    int t   = rem >> 5;
    long long tok = g_trg64 ? ((const long long*)trg)[b*T_ + t]
                            : (long long)((const int*)trg)[b*T_ + t];
    g_xe[idx] = emb[(size_t)tok*E_ + e];
}

__global__ void k_init(const float* __restrict__ h0){
    int i = blockIdx.x*256 + threadIdx.x;
    g_h[0][i] = h0[i];
}

__global__ void k_wqb(const float* __restrict__ Wb, const float* __restrict__ Wq){
    __shared__ float A[16][17], Bm[16][17];
    int tx = threadIdx.x, ty = threadIdx.y;
    int i = blockIdx.y*16 + ty, k = blockIdx.x*16 + tx;
    float acc = 0.f;
    for (int m0 = 0; m0 < H_; m0 += 16){
        A [ty][tx] = Wb[i*H_ + m0 + tx];
        Bm[ty][tx] = Wq[(m0+ty)*H_ + k];
        __syncthreads();
#pragma unroll
        for (int m = 0; m < 16; m++) acc += A[ty][m]*Bm[m][tx];
        __syncthreads();
    }
    g_Wqb[i*H_ + k] = acc;
}

__global__ void k_bqb(const float* __restrict__ Wb, const float* __restrict__ bq,
                      const float* __restrict__ bb){
    int row  = blockIdx.x*4 + (threadIdx.x >> 5);
    int lane = threadIdx.x & 31;
    float s = 0.f;
    for (int m = lane; m < H_; m += 32) s += Wb[row*H_ + m]*bq[m];
#pragma unroll
    for (int o = 16; o; o >>= 1) s += __shfl_xor_sync(0xffffffffu, s, o);
    if (lane == 0) g_bqb[row] = s + bb[row];
}

// mem2[r][k] = sum_i m[r][i] * Wqb[i][k]   (r over B*S rows)
__global__ __launch_bounds__(256) void k_mem2(const float* __restrict__ mem){
    __shared__ float Am[64][17];
    __shared__ float Bm[16][68];
    int tx = threadIdx.x & 15, ty = threadIdx.x >> 4;
    int r0 = blockIdx.y*64, k0 = blockIdx.x*64;
    float acc[4][4] = {};
    for (int i0 = 0; i0 < H_; i0 += 16){
        for (int l = threadIdx.x; l < 1024; l += 256){
            int rr = l >> 4, ii = l & 15;
            Am[rr][ii] = mem[(size_t)(r0+rr)*H_ + i0 + ii];
        }
        for (int l = threadIdx.x; l < 1024; l += 256){
            int ii = l >> 6, kk = l & 63;
            Bm[ii][kk] = g_Wqb[(size_t)(i0+ii)*H_ + k0 + kk];
        }
        __syncthreads();
#pragma unroll
        for (int ii = 0; ii < 16; ii++){
            float av[4], bv[4];
#pragma unroll
            for (int p = 0; p < 4; p++) av[p] = Am[ty*4+p][ii];
#pragma unroll
            for (int p = 0; p < 4; p++) bv[p] = Bm[ii][tx*4+p];
#pragma unroll
            for (int p = 0; p < 4; p++)
#pragma unroll
            for (int q = 0; q < 4; q++) acc[p][q] += av[p]*bv[q];
        }
        __syncthreads();
    }
#pragma unroll
    for (int p = 0; p < 4; p++)
#pragma unroll
    for (int q = 0; q < 4; q++)
        g_mem2[(size_t)(r0+ty*4+p)*H_ + k0 + tx*4 + q] = acc[p][q];
}

__global__ void k_sb(const float* __restrict__ mem){
    int row  = blockIdx.x*8 + (threadIdx.x >> 5);
    int lane = threadIdx.x & 31;
    const float* m = mem + (size_t)row*H_;
    float s = 0.f;
    for (int i = lane; i < H_; i += 32) s += g_bqb[i]*m[i];
#pragma unroll
    for (int o = 16; o; o >>= 1) s += __shfl_xor_sync(0xffffffffu, s, o);
    if (lane == 0) g_sb[row] = s;
}

// --------------------------- grid barrier (flag/release) ---------------------
__device__ __forceinline__ void gbar(int blk, unsigned long long epoch){
    __syncthreads();
    if (blk == 0){
        if (threadIdx.x == 0) st_rel(&g_flag[0], epoch);
        if (threadIdx.x < NBLK){
            while (ld_acq(&g_flag[threadIdx.x]) < epoch) { }
        }
        __syncthreads();
        if (threadIdx.x == 0) st_rel(&g_rel, epoch);
    } else {
        if (threadIdx.x == 0){
            st_rel(&g_flag[blk], epoch);
            while (ld_acq(&g_rel) < epoch) { }
        }
    }
    __syncthreads();
}

// ---------- X staging macros (32 rows x 64 K chunk, double buffered) ---------
#define X_STS(c) { \
    _Pragma("unroll") \
    for (int i_ = 0; i_ < 2; i_++){ \
        int f_ = threadIdx.x*2 + i_; int bl_ = f_ >> 4; int kk4_ = (f_ & 15)*4; \
        *(float4*)(XS + (((c)&1)*32 + bl_)*68 + kk4_) = pre[i_]; } }

// ------------- skinny phase: 4 rows x 32 b, r1 c4 kp8 tiling -----------------
__device__ __forceinline__ void phase_skinny2(
    float* XS, const float* Wsm, int nch,
    const float* X0, const float* X1, int ctx4,
    const float* bias, int row0, float* dst, bool do_tanh)
{
    int tid = threadIdx.x;
    int bgw = tid >> 5, rg = (tid >> 3) & 3, kp = tid & 7;
    int K = nch*64;
    float4 pre[2];
#define SK_LOAD(c) { \
    _Pragma("unroll") \
    for (int i_ = 0; i_ < 2; i_++){ \
        int f_ = tid*2 + i_; int bl_ = f_ >> 4; int kk4_ = (f_ & 15)*4; \
        int kg_ = (c)*64 + kk4_; \
        if (kg_ < 512){ \
            pre[i_] = __ldcg((const float4*)(X0 + bl_*512 + kg_)); \
        } else if (!ctx4){ \
            pre[i_] = __ldcg((const float4*)(X1 + bl_*512 + (kg_-512))); \
        } else { \
            const float4* p_ = (const float4*)(X1 + bl_*512 + (kg_-512)); \
            float4 v0 = __ldcg(p_); \
            float4 v1 = __ldcg(p_ + BH/4); \
            float4 v2 = __ldcg(p_ + 2*(BH/4)); \
            float4 v3 = __ldcg(p_ + 3*(BH/4)); \
            pre[i_] = make_float4(v0.x+v1.x+v2.x+v3.x, v0.y+v1.y+v2.y+v3.y, \
                                  v0.z+v1.z+v2.z+v3.z, v0.w+v1.w+v2.w+v3.w); \
        } } }
    float a0 = 0.f, a1 = 0.f, a2 = 0.f, a3 = 0.f;
    SK_LOAD(0); X_STS(0); __syncthreads();
    for (int c = 0; c < nch; c++){
        if (c+1 < nch) SK_LOAD(c+1);
        const float* xb = XS + ((c&1)*32 + bgw*4)*68 + kp*4;
        const float* wb = Wsm + rg*K + c*64 + kp*4;
#pragma unroll
        for (int j = 0; j < 2; j++){
            float4 w  = *(const float4*)(wb + j*32);
            float4 x0 = *(const float4*)(xb + 0*68 + j*32);
            float4 x1 = *(const float4*)(xb + 1*68 + j*32);
            float4 x2 = *(const float4*)(xb + 2*68 + j*32);
            float4 x3 = *(const float4*)(xb + 3*68 + j*32);
            a0 += w.x*x0.x + w.y*x0.y + w.z*x0.z + w.w*x0.w;
            a1 += w.x*x1.x + w.y*x1.y + w.z*x1.z + w.w*x1.w;
            a2 += w.x*x2.x + w.y*x2.y + w.z*x2.z + w.w*x2.w;
            a3 += w.x*x3.x + w.y*x3.y + w.z*x3.z + w.w*x3.w;
        }
        if (c+1 < nch){ X_STS(c+1); __syncthreads(); }
    }
#pragma unroll
    for (int o = 4; o; o >>= 1){
        a0 += __shfl_down_sync(0xffffffffu, a0, o);
        a1 += __shfl_down_sync(0xffffffffu, a1, o);
        a2 += __shfl_down_sync(0xffffffffu, a2, o);
        a3 += __shfl_down_sync(0xffffffffu, a3, o);
    }
    if (kp == 0){
        float bs = bias[row0 + rg];
        float v0 = a0 + bs, v1 = a1 + bs, v2 = a2 + bs, v3 = a3 + bs;
        if (do_tanh){ v0 = tanhf(v0); v1 = tanhf(v1); v2 = tanhf(v2); v3 = tanhf(v3); }
        dst[(bgw*4+0)*512 + row0 + rg] = v0;
        dst[(bgw*4+1)*512 + row0 + rg] = v1;
        dst[(bgw*4+2)*512 + row0 + rg] = v2;
        dst[(bgw*4+3)*512 + row0 + rg] = v3;
    }
#undef SK_LOAD
    __syncthreads();
}

// -------------------- the persistent 64-step chain kernel -------------------
__global__ __launch_bounds__(NTHR, 1) void k_persist(
    const float* __restrict__ W_ih, const float* __restrict__ W_hh,
    const float* __restrict__ b_ih, const float* __restrict__ b_hh,
    const float* __restrict__ Wo1,  const float* __restrict__ bo1,
    const float* __restrict__ Wo2,  const float* __restrict__ bo2,
    const float* __restrict__ src_memory, const void* __restrict__ mask,
    const float* __restrict__ init_cell,  const float* __restrict__ init_output)
{
    extern __shared__ float smem[];
    float* SW  = smem + OFF_SW;
    float* SM  = smem + OFF_SM;
    float* SO1 = smem + OFF_SO1;
    float* SO2 = smem + OFF_SO2;
    float* XS  = smem + OFF_XS;
    float* SCR = smem + OFF_SCR;
    float* SC  = smem + OFF_SC;

    int tid = threadIdx.x;
    int blk = blockIdx.x;
    int u0  = blk*4;               // unit / row base for row-partitioned phases
    int ab  = blk & 31;            // attn batch
    int sq  = blk >> 5;            // attn s-quad
    int bgw = tid >> 5, rg = (tid >> 3) & 3, kp = tid & 7;

    unsigned long long ebase = ld_acq(&g_ebase);
    unsigned long long ep = ebase;

    // ---------------- one-time smem population ----------------
    for (int idx = tid; idx < 6144; idx += NTHR){      // 16 gate rows x 384 float4
        int r = idx / 384, j = idx % 384;
        int grow = (r >> 2)*512 + u0 + (r & 3);
        int kg = j*4;
        float4 v = (kg < 1024) ? *(const float4*)(W_ih + (size_t)grow*1024 + kg)
                               : *(const float4*)(W_hh + (size_t)grow*512 + (kg-1024));
        *(float4*)(SW + r*1544 + kg) = v;
    }
    for (int idx = tid; idx < 3200; idx += NTHR){      // 25 s x 128 float4
        int i = idx >> 7, j = idx & 127;
        float4 v = *(const float4*)(src_memory + ((size_t)ab*S_ + sq*25 + i)*H_ + j*4);
        *(float4*)(SM + i*516 + j*4) = v;
    }
    for (int idx = tid; idx < 1024; idx += NTHR){      // Wo1 4 rows x 256 float4
        int rr = idx >> 8, j = idx & 255;
        *(float4*)(SO1 + rr*1024 + j*4) = *(const float4*)(Wo1 + (size_t)(u0+rr)*1024 + j*4);
    }
    for (int idx = tid; idx < 512; idx += NTHR){       // Wo2 4 rows x 128 float4
        int rr = idx >> 7, j = idx & 127;
        *(float4*)(SO2 + rr*512 + j*4) = *(const float4*)(Wo2 + (size_t)(u0+rr)*512 + j*4);
    }
    if (tid < 128){                                    // cell init [uu*32 + b]
        int uu = tid >> 5, b = tid & 31;
        SC[tid] = init_cell[b*H_ + u0 + uu];
    }
    __syncthreads();

    for (int t = 0; t < T_; t++){
        // ---------------- phase A: gates GEMM (r4 c4 kp8) + LSTM cell --------
        {
            const float* xe_t    = g_xe + (size_t)t*BE;
            const float* outprev = t ? g_outs + (size_t)(t-1)*BE : init_output;
            const float* hprev   = g_h[t & 1];
            float4 pre[2];
#define G_LOAD(c) { \
    _Pragma("unroll") \
    for (int i_ = 0; i_ < 2; i_++){ \
        int f_ = tid*2 + i_; int bl_ = f_ >> 4; int kk4_ = (f_ & 15)*4; \
        int kg_ = (c)*64 + kk4_; \
        const float* s_ = (kg_ < 512)  ? xe_t    + bl_*512 + kg_ \
                        : (kg_ < 1024) ? outprev + bl_*512 + (kg_-512) \
                                       : hprev   + bl_*512 + (kg_-1024); \
        pre[i_] = __ldcg((const float4*)s_); } }
            float acc[4][4];
#pragma unroll
            for (int rr = 0; rr < 4; rr++)
#pragma unroll
            for (int bb = 0; bb < 4; bb++) acc[rr][bb] = 0.f;

            G_LOAD(0); X_STS(0); __syncthreads();
            for (int c = 0; c < 24; c++){
                if (c < 23) G_LOAD(c+1);
                const float* xb = XS + ((c&1)*32 + bgw*4)*68 + kp*4;
                const float* wb = SW + c*64 + kp*4;
#pragma unroll
                for (int j = 0; j < 2; j++){
                    float4 x[4], w[4];
#pragma unroll
                    for (int bb = 0; bb < 4; bb++)
                        x[bb] = *(const float4*)(xb + bb*68 + j*32);
#pragma unroll
                    for (int rr = 0; rr < 4; rr++)
                        w[rr] = *(const float4*)(wb + (rr*4+rg)*1544 + j*32);
#pragma unroll
                    for (int rr = 0; rr < 4; rr++)
#pragma unroll
                    for (int bb = 0; bb < 4; bb++)
                        acc[rr][bb] += w[rr].x*x[bb].x + w[rr].y*x[bb].y
                                     + w[rr].z*x[bb].z + w[rr].w*x[bb].w;
                }
                if (c < 23){ X_STS(c+1); __syncthreads(); }
            }
            // reduce over kp (lane octets), write SCR[row*33 + b]
#pragma unroll
            for (int rr = 0; rr < 4; rr++)
#pragma unroll
            for (int bb = 0; bb < 4; bb++){
                float v = acc[rr][bb];
                v += __shfl_down_sync(0xffffffffu, v, 4);
                v += __shfl_down_sync(0xffffffffu, v, 2);
                v += __shfl_down_sync(0xffffffffu, v, 1);
                if (kp == 0) SCR[(rr*4+rg)*33 + bgw*4+bb] = v;
            }
            __syncthreads();
            if (tid < 128){
                int uu = tid >> 5, b = tid & 31;
                int u  = u0 + uu;
                float iv = SCR[(0*4+uu)*33 + b] + b_ih[u]         + b_hh[u];
                float fv = SCR[(1*4+uu)*33 + b] + b_ih[512 + u]   + b_hh[512 + u];
                float gv = SCR[(2*4+uu)*33 + b] + b_ih[1024 + u]  + b_hh[1024 + u];
                float ov = SCR[(3*4+uu)*33 + b] + b_ih[1536 + u]  + b_hh[1536 + u];
                float is = 1.f/(1.f + expf(-iv));
                float fs = 1.f/(1.f + expf(-fv));
                float os = 1.f/(1.f + expf(-ov));
                float gt = tanhf(gv);
                float cn = fs*SC[tid] + is*gt;
                SC[tid] = cn;
                g_h[(t+1) & 1][b*H_ + u] = os*tanhf(cn);
            }
#undef G_LOAD
        }
        gbar(blk, ++ep);

        // -------- phase B: scores_s = h . mem2[b][s] + sb[b][s]  (25 s/block) ----
        {
            if (tid < 128)
                ((float4*)SCR)[tid] = __ldcg(((const float4*)(g_h[(t+1)&1] + ab*H_)) + tid);
            __syncthreads();
            int w = tid >> 5, lane = tid & 31;
            for (int si = w; si < 25; si += 8){
                int sg = sq*25 + si;
                const float* m2 = g_mem2 + ((size_t)ab*100 + sg)*H_;
                float sum = 0.f;
#pragma unroll
                for (int j = 0; j < 4; j++){
                    int k = lane*4 + j*128;
                    float4 qv = *(const float4*)(SCR + k);
                    float4 mv = *(const float4*)(m2 + k);
                    sum += qv.x*mv.x + qv.y*mv.y + qv.z*mv.z + qv.w*mv.w;
                }
#pragma unroll
                for (int o = 16; o; o >>= 1) sum += __shfl_xor_sync(0xffffffffu, sum, o);
                if (lane == 0){
                    bool mv_ = g_mask4 ? (((const int*)mask)[ab*S_ + sg] != 0)
                                       : (((const unsigned char*)mask)[ab*S_ + sg] != 0);
                    g_sc[ab*100 + sg] = mv_ ? (sum + g_sb[ab*100 + sg]) : -1e9f;
                }
            }
        }
        gbar(blk, ++ep);

        // -------- phase C: softmax (redundant) + partial ctx over own quad --------
        {
            if (tid < 25)
                ((float4*)SCR)[tid] = __ldcg((const float4*)(g_sc + ab*100 + tid*4));
            __syncthreads();
            if (tid < 32){
                int lane = tid;
                float mx = -1e30f;
#pragma unroll
                for (int j = 0; j < 4; j++){
                    int s = lane + j*32;
                    if (s < 100) mx = fmaxf(mx, SCR[s]);
                }
#pragma unroll
                for (int o = 16; o; o >>= 1) mx = fmaxf(mx, __shfl_xor_sync(0xffffffffu, mx, o));
                float ps = 0.f;
#pragma unroll
                for (int j = 0; j < 4; j++){
                    int s = lane + j*32;
                    if (s < 100) ps += expf(SCR[s] - mx);
                }
#pragma unroll
                for (int o = 16; o; o >>= 1) ps += __shfl_xor_sync(0xffffffffu, ps, o);
                if (lane == 0){ SCR[120] = mx; SCR[121] = 1.f/ps; }
            }
            __syncthreads();
            if (tid < 25)
                SCR[128 + tid] = expf(SCR[sq*25 + tid] - SCR[120]) * SCR[121];
            __syncthreads();
            float c0 = 0.f, c1 = 0.f;
            int h0 = tid, h1 = tid + 256;
            for (int s = 0; s < 25; s++){
                float ws = SCR[128 + s];
                c0 += ws * SM[s*516 + h0];
                c1 += ws * SM[s*516 + h1];
            }
            g_ctxp[sq*BH + ab*H_ + h0] = c0;
            g_ctxp[sq*BH + ab*H_ + h1] = c1;
        }
        gbar(blk, ++ep);

        // ---- phase D: t1 = tanh([h; sum4(ctxp)] @ Wo1^T + bo1) ----
        phase_skinny2(XS, SO1, 16, g_h[(t+1)&1], g_ctxp, 1, bo1, u0, g_t1, true);
        gbar(blk, ++ep);

        // ---- phase E: out = t1 @ Wo2^T + bo2 ----
        phase_skinny2(XS, SO2, 8, g_t1, (const float*)0, 0, bo2, u0,
                      g_outs + (size_t)t*BE, false);
        gbar(blk, ++ep);
    }

    if (blk == 0 && tid == 0) st_rel(&g_ebase, ebase + 1024);
}

// ---------------- tf32 logits GEMM: (2048 x 32000) @ K=512 -----------------
__device__ __forceinline__ unsigned f2t(float f){
    unsigned u;
    asm("cvt.rna.tf32.f32 %0, %1;" : "=r"(u) : "f"(f));
    return u;
}

__global__ __launch_bounds__(256) void k_logits(const float* __restrict__ emb,
                                                float* __restrict__ out){
    __shared__ unsigned As[128][36];
    __shared__ unsigned Bs[128][36];
    int tid = threadIdx.x;
    int m0 = blockIdx.y*128;
    int n0 = blockIdx.x*128;
    int warp = tid >> 5, lane = tid & 31;
    int wm = (warp & 1)*64, wn = (warp >> 1)*32;
    int g = lane >> 2, tg = lane & 3;
    float c[4][4][4];
#pragma unroll
    for (int mt = 0; mt < 4; mt++)
#pragma unroll
    for (int nt = 0; nt < 4; nt++)
#pragma unroll
    for (int r = 0; r < 4; r++) c[mt][nt][r] = 0.f;

    for (int kc = 0; kc < 16; kc++){
        int k0 = kc*32;
#pragma unroll
        for (int i = 0; i < 4; i++){
            int f = tid + i*256;
            int r = f >> 3, k4 = (f & 7)*4;
            float4 va = *(const float4*)(g_outs + (size_t)(m0+r)*512 + k0 + k4);
            As[r][k4]   = f2t(va.x); As[r][k4+1] = f2t(va.y);
            As[r][k4+2] = f2t(va.z); As[r][k4+3] = f2t(va.w);
            float4 vb = *(const float4*)(emb + (size_t)(n0+r)*512 + k0 + k4);
            Bs[r][k4]   = f2t(vb.x); Bs[r][k4+1] = f2t(vb.y);
            Bs[r][k4+2] = f2t(vb.z); Bs[r][k4+3] = f2t(vb.w);
        }
        __syncthreads();
#pragma unroll
        for (int ks = 0; ks < 4; ks++){
            unsigned a[4][4], bf[4][2];
#pragma unroll
            for (int mt = 0; mt < 4; mt++){
                int rr = wm + mt*16 + g;
                a[mt][0] = As[rr  ][ks*8+tg];
                a[mt][1] = As[rr+8][ks*8+tg];
                a[mt][2] = As[rr  ][ks*8+tg+4];
                a[mt][3] = As[rr+8][ks*8+tg+4];
            }
#pragma unroll
            for (int nt = 0; nt < 4; nt++){
                int rr = wn + nt*8 + g;
                bf[nt][0] = Bs[rr][ks*8+tg];
                bf[nt][1] = Bs[rr][ks*8+tg+4];
            }
#pragma unroll
            for (int mt = 0; mt < 4; mt++)
#pragma unroll
            for (int nt = 0; nt < 4; nt++){
                asm volatile(
                    "mma.sync.aligned.m16n8k8.row.col.f32.tf32.tf32.f32 "
                    "{%0,%1,%2,%3}, {%4,%5,%6,%7}, {%8,%9}, {%0,%1,%2,%3};\n"
                    : "+f"(c[mt][nt][0]), "+f"(c[mt][nt][1]),
                      "+f"(c[mt][nt][2]), "+f"(c[mt][nt][3])
                    : "r"(a[mt][0]), "r"(a[mt][1]), "r"(a[mt][2]), "r"(a[mt][3]),
                      "r"(bf[nt][0]), "r"(bf[nt][1]));
            }
        }
        __syncthreads();
    }
#pragma unroll
    for (int mt = 0; mt < 4; mt++){
        int m1 = m0 + wm + mt*16 + g;
        int m2 = m1 + 8;
        int t1 = m1 >> 5, b1 = m1 & 31;
        int t2 = m2 >> 5, b2 = m2 & 31;
#pragma unroll
        for (int nt = 0; nt < 4; nt++){
            int n = n0 + wn + nt*8 + tg*2;
            float2* p1 = (float2*)(out + (size_t)b1*T_*V_ + (size_t)t1*V_ + n);
            *p1 = make_float2(c[mt][nt][0], c[mt][nt][1]);
            float2* p2 = (float2*)(out + (size_t)b2*T_*V_ + (size_t)t2*V_ + n);
            *p2 = make_float2(c[mt][nt][2], c[mt][nt][3]);
        }
    }
}

// ------------------------------- launch ------------------------------------
extern "C" void kernel_launch(void* const* d_in, const int* in_sizes, int n_in,
                              void* d_out, int out_size){
    const float* src_memory  = (const float*)d_in[0];
    const void*  src_mask    = d_in[1];
    const float* init_hidden = (const float*)d_in[2];
    const float* init_cell   = (const float*)d_in[3];
    const float* init_output = (const float*)d_in[4];
    const void*  trg         = d_in[5];
    const float* emb         = (const float*)d_in[6];
    const float* W_ih        = (const float*)d_in[7];
    const float* W_hh        = (const float*)d_in[8];
    const float* b_ih        = (const float*)d_in[9];
    const float* b_hh        = (const float*)d_in[10];
    const float* Wq          = (const float*)d_in[11];
    const float* bq          = (const float*)d_in[12];
    const float* Wb          = (const float*)d_in[13];
    const float* bb          = (const float*)d_in[14];
    const float* Wo1         = (const float*)d_in[15];
    const float* bo1         = (const float*)d_in[16];
    const float* Wo2         = (const float*)d_in[17];
    const float* bo2         = (const float*)d_in[18];
    float* out = (float*)d_out;

    cudaFuncSetAttribute(k_persist,
        cudaFuncAttributeMaxDynamicSharedMemorySize, SMEM_BYTES);

    k_detect<<<1, 32>>>(trg, src_mask);
    k_gather<<<(T_*B_*E_)/256, 256>>>(trg, emb);
    k_init<<<BH/256, 256>>>(init_hidden);
    k_wqb<<<dim3(32,32), dim3(16,16)>>>(Wb, Wq);
    k_bqb<<<128, 128>>>(Wb, bq, bb);
    k_mem2<<<dim3(H_/64, (B_*S_)/64), 256>>>(src_memory);
    k_sb<<<(B_*S_)/8, 256>>>(src_memory);

    k_persist<<<NBLK, NTHR, SMEM_BYTES>>>(
        W_ih, W_hh, b_ih, b_hh, Wo1, bo1, Wo2, bo2,
        src_memory, src_mask, init_cell, init_output);

    k_logits<<<dim3(V_/128, (T_*B_)/128), 256>>>(emb, out);
}